// round 13
// baseline (speedup 1.0000x reference)
#include <cuda_runtime.h>
#include <cuda_bf16.h>

#define NNODES 100000
#define NEDGES 1600000
#define DH 128
#define DOUT 64
#define BN_EPS 1e-5f

#define TM 64
#define GEMM_THREADS 256
#define XS_STRIDE 132                 // 64 rows  (A tile), bank-spread pad
#define WS_STRIDE 136                 // 128 rows (B tile), bank-spread pad
#define GEMM_SMEM ((DH * WS_STRIDE + TM * XS_STRIDE) * 4)   // ~103.4 KB
#define GRID_GEMM ((NNODES + TM - 1) / TM)

// ---------------- device scratch ----------------
struct alignas(8) Edge { int s; float w; };

__device__ __nv_bfloat16 g_hb[(long)NNODES * DH];  // GEMM output (bf16)
__device__ float g_agg[(long)NNODES * DH];   // aggregation buffer (fp32)
__device__ float g_s[NNODES];                // per-src edge-weight sums
__device__ float g_stats[2 * DH];            // column sum / sumsq
__device__ float g_scale[DH];                // BN fused scale
__device__ float g_shift[DH];                // BN fused shift
__device__ float g_t[DH];                    // s^T x1
__device__ int   g_rowptr[NNODES + 1];       // CSR by dst
__device__ int   g_cnt[NNODES];              // histogram / fill cursor
__device__ Edge  g_csr[NEDGES];              // packed (src, weight)

__device__ __forceinline__ unsigned tf32_of(float f) {
    unsigned r;
    asm("cvt.rna.tf32.f32 %0, %1;" : "=r"(r) : "f"(f));
    return r;
}

#define MMA_TF32(d, a, b)                                                    \
    asm volatile(                                                            \
        "mma.sync.aligned.m16n8k8.row.col.f32.tf32.tf32.f32 "                \
        "{%0,%1,%2,%3}, {%4,%5,%6,%7}, {%8,%9}, {%0,%1,%2,%3};"              \
        : "+f"((d)[0]), "+f"((d)[1]), "+f"((d)[2]), "+f"((d)[3])             \
        : "r"((a)[0]), "r"((a)[1]), "r"((a)[2]), "r"((a)[3]),                \
          "r"((b)[0]), "r"((b)[1]))

// ---------------- init: counters, s, stats, t -------------------------------
__global__ void zero_init_kernel() {
    int i = blockIdx.x * blockDim.x + threadIdx.x;
    int stride = gridDim.x * blockDim.x;
    for (int j = i; j < NNODES; j += stride) { g_cnt[j] = 0; g_s[j] = 0.f; }
    if (i < 2 * DH)       g_stats[i] = 0.f;
    else if (i < 3 * DH)  g_t[i - 2 * DH] = 0.f;
}

// ---------------- histogram by dst, fused per-src weight sums ---------------
__global__ void hist_kernel(const int* __restrict__ src,
                            const int* __restrict__ dst,
                            const float* __restrict__ ew) {
    int e = blockIdx.x * blockDim.x + threadIdx.x;
    if (e < NEDGES) {
        atomicAdd(&g_cnt[dst[e]], 1);
        atomicAdd(&g_s[src[e]], ew[e]);
    }
}

// ---------------- exclusive scan of g_cnt -> g_rowptr (single block) --------
__global__ void scan_kernel() {
    __shared__ int ssums[1024];
    const int CH = (NNODES + 1023) / 1024;
    int t = threadIdx.x;
    int base = t * CH;
    int lim = min(base + CH, NNODES);
    int s = 0;
    for (int i = base; i < lim; i++) s += g_cnt[i];
    ssums[t] = s;
    __syncthreads();
    for (int off = 1; off < 1024; off <<= 1) {
        int v = (t >= off) ? ssums[t - off] : 0;
        __syncthreads();
        ssums[t] += v;
        __syncthreads();
    }
    int run = t ? ssums[t - 1] : 0;
    for (int i = base; i < lim; i++) {
        int c = g_cnt[i];
        g_rowptr[i] = run;
        g_cnt[i] = run;          // fill cursor
        run += c;
    }
    if (t == 0) g_rowptr[NNODES] = ssums[1023];
}

// ---------------- fill CSR (single 8B store per edge) ------------------------
__global__ void fill_kernel(const int* __restrict__ src,
                            const int* __restrict__ dst,
                            const float* __restrict__ ew) {
    int e = blockIdx.x * blockDim.x + threadIdx.x;
    if (e < NEDGES) {
        int pos = atomicAdd(&g_cnt[dst[e]], 1);
        Edge ed; ed.s = src[e]; ed.w = ew[e];
        g_csr[pos] = ed;
    }
}

// ---------------- GEMM: g_hb = X @ W via TF32 tensor-core mma ---------------
// mode 0: X = Xext (raw); mode 1: X = relu(g_agg*scale+shift)
__global__ void gemm_kernel(const float* __restrict__ Xext,
                            const float* __restrict__ W, int mode) {
    extern __shared__ unsigned smem_u[];
    unsigned* ws = smem_u;                        // [128][WS_STRIDE] tf32
    unsigned* xs = smem_u + DH * WS_STRIDE;       // [64][XS_STRIDE]  tf32

    const int tid = threadIdx.x;
    const float* X = mode ? g_agg : Xext;

    // ---- stage W (k-major) as tf32
    for (int i = tid; i < DH * DH / 4; i += GEMM_THREADS) {
        int k  = i >> 5;          // 32 float4 per row
        int c4 = (i & 31) << 2;
        float4 v = ((const float4*)W)[i];
        uint4 o;
        o.x = tf32_of(v.x); o.y = tf32_of(v.y);
        o.z = tf32_of(v.z); o.w = tf32_of(v.w);
        *(uint4*)(ws + k * WS_STRIDE + c4) = o;
    }

    // ---- stage X tile (with fused BN+ReLU for mode 1) as tf32
    const int row0 = blockIdx.x * TM;
    for (int i = tid; i < TM * DH / 4; i += GEMM_THREADS) {
        int r  = i >> 5;
        int c4 = (i & 31) << 2;
        float4 v = make_float4(0.f, 0.f, 0.f, 0.f);
        if (row0 + r < NNODES) {
            v = *(const float4*)(X + (long)(row0 + r) * DH + c4);
            if (mode) {
                v.x = fmaxf(0.f, fmaf(v.x, g_scale[c4 + 0], g_shift[c4 + 0]));
                v.y = fmaxf(0.f, fmaf(v.y, g_scale[c4 + 1], g_shift[c4 + 1]));
                v.z = fmaxf(0.f, fmaf(v.z, g_scale[c4 + 2], g_shift[c4 + 2]));
                v.w = fmaxf(0.f, fmaf(v.w, g_scale[c4 + 3], g_shift[c4 + 3]));
            }
        }
        uint4 o;
        o.x = tf32_of(v.x); o.y = tf32_of(v.y);
        o.z = tf32_of(v.z); o.w = tf32_of(v.w);
        *(uint4*)(xs + r * XS_STRIDE + c4) = o;
    }
    __syncthreads();

    const int lane = tid & 31;
    const int warp = tid >> 5;
    const int mrow = (warp & 1) * 32;     // row offset of this warp's 32 rows
    const int ncol = (warp >> 1) * 32;    // col offset of this warp's 32 cols

    float acc[2][4][4];
#pragma unroll
    for (int mi = 0; mi < 2; mi++)
#pragma unroll
        for (int ni = 0; ni < 4; ni++)
#pragma unroll
            for (int j = 0; j < 4; j++) acc[mi][ni][j] = 0.f;

    const int ar = mrow + (lane >> 2);    // A fragment row (within tile)
    const int ak = lane & 3;              // A fragment col (within k-step)
    const int bn = ncol + (lane >> 2);    // B fragment col
    const int bk = lane & 3;              // B fragment row (within k-step)

#pragma unroll 4
    for (int k0 = 0; k0 < DH; k0 += 8) {
        unsigned a[2][4], b[4][2];
#pragma unroll
        for (int mi = 0; mi < 2; mi++) {
            const unsigned* ab = xs + (ar + 16 * mi) * XS_STRIDE + k0 + ak;
            a[mi][0] = ab[0];
            a[mi][1] = ab[8 * XS_STRIDE];
            a[mi][2] = ab[4];
            a[mi][3] = ab[8 * XS_STRIDE + 4];
        }
#pragma unroll
        for (int ni = 0; ni < 4; ni++) {
            const unsigned* bb = ws + (k0 + bk) * WS_STRIDE + bn + 8 * ni;
            b[ni][0] = bb[0];
            b[ni][1] = bb[4 * WS_STRIDE];
        }
#pragma unroll
        for (int mi = 0; mi < 2; mi++)
#pragma unroll
            for (int ni = 0; ni < 4; ni++)
                MMA_TF32(acc[mi][ni], a[mi], b[ni]);
    }

    // ---- epilogue: bf16 pairs. c0,c1 at (r, cc); c2,c3 at (r+8, cc)
#pragma unroll
    for (int mi = 0; mi < 2; mi++) {
        int r0 = row0 + mrow + 16 * mi + (lane >> 2);
        int r1 = r0 + 8;
#pragma unroll
        for (int ni = 0; ni < 4; ni++) {
            int cc = ncol + 8 * ni + 2 * (lane & 3);
            if (r0 < NNODES)
                *(__nv_bfloat162*)(g_hb + (long)r0 * DH + cc) =
                    __floats2bfloat162_rn(acc[mi][ni][0], acc[mi][ni][1]);
            if (r1 < NNODES)
                *(__nv_bfloat162*)(g_hb + (long)r1 * DH + cc) =
                    __floats2bfloat162_rn(acc[mi][ni][2], acc[mi][ni][3]);
        }
    }
}

// ---------------- CSR gather-aggregate (bf16 rows) with fused stats ---------
// one warp per node; lane owns 4 columns; 4 edges in flight
__device__ __forceinline__ void acc_edge(float4& acc, uint2 u, float w) {
    float2 f01 = __bfloat1622float2(*(__nv_bfloat162*)&u.x);
    float2 f23 = __bfloat1622float2(*(__nv_bfloat162*)&u.y);
    acc.x = fmaf(w, f01.x, acc.x); acc.y = fmaf(w, f01.y, acc.y);
    acc.z = fmaf(w, f23.x, acc.z); acc.w = fmaf(w, f23.y, acc.w);
}

__global__ void gather_kernel() {
    __shared__ float sred[8][DH];
    __shared__ float sred2[8][DH];
    const int tid = threadIdx.x;
    const int lane = tid & 31;
    const int warp = tid >> 5;

    float4 lsum = make_float4(0.f, 0.f, 0.f, 0.f);
    float4 lsq  = make_float4(0.f, 0.f, 0.f, 0.f);

    for (int n = blockIdx.x * 8 + warp; n < NNODES; n += gridDim.x * 8) {
        int beg = g_rowptr[n], end = g_rowptr[n + 1];
        float4 acc = make_float4(0.f, 0.f, 0.f, 0.f);
        int j = beg;
        for (; j + 4 <= end; j += 4) {
            Edge e0 = g_csr[j],     e1 = g_csr[j + 1];
            Edge e2 = g_csr[j + 2], e3 = g_csr[j + 3];
            uint2 u0 = ((const uint2*)(g_hb + (long)e0.s * DH))[lane];
            uint2 u1 = ((const uint2*)(g_hb + (long)e1.s * DH))[lane];
            uint2 u2 = ((const uint2*)(g_hb + (long)e2.s * DH))[lane];
            uint2 u3 = ((const uint2*)(g_hb + (long)e3.s * DH))[lane];
            acc_edge(acc, u0, e0.w);
            acc_edge(acc, u1, e1.w);
            acc_edge(acc, u2, e2.w);
            acc_edge(acc, u3, e3.w);
        }
        for (; j < end; j++) {
            Edge e0 = g_csr[j];
            uint2 u0 = ((const uint2*)(g_hb + (long)e0.s * DH))[lane];
            acc_edge(acc, u0, e0.w);
        }
        ((float4*)(g_agg + (long)n * DH))[lane] = acc;

        lsum.x += acc.x; lsum.y += acc.y; lsum.z += acc.z; lsum.w += acc.w;
        lsq.x = fmaf(acc.x, acc.x, lsq.x); lsq.y = fmaf(acc.y, acc.y, lsq.y);
        lsq.z = fmaf(acc.z, acc.z, lsq.z); lsq.w = fmaf(acc.w, acc.w, lsq.w);
    }

    sred[warp][lane * 4 + 0] = lsum.x;  sred2[warp][lane * 4 + 0] = lsq.x;
    sred[warp][lane * 4 + 1] = lsum.y;  sred2[warp][lane * 4 + 1] = lsq.y;
    sred[warp][lane * 4 + 2] = lsum.z;  sred2[warp][lane * 4 + 2] = lsq.z;
    sred[warp][lane * 4 + 3] = lsum.w;  sred2[warp][lane * 4 + 3] = lsq.w;
    __syncthreads();
    if (tid < DH) {
        float a = 0.f, b = 0.f;
#pragma unroll
        for (int w = 0; w < 8; w++) { a += sred[w][tid]; b += sred2[w][tid]; }
        atomicAdd(&g_stats[tid], a);
        atomicAdd(&g_stats[DH + tid], b);
    }
}

// ---------------- BN parameters (conv bias cancels in BN); self-resets ------
__global__ void bnparams_kernel(const float* __restrict__ gamma,
                                const float* __restrict__ beta) {
    int c = threadIdx.x;   // 128 threads
    float mean = g_stats[c] * (1.0f / NNODES);
    float var  = g_stats[DH + c] * (1.0f / NNODES) - mean * mean;
    float sc   = gamma[c] * rsqrtf(var + BN_EPS);
    g_scale[c] = sc;
    g_shift[c] = beta[c] - mean * sc;
    g_stats[c] = 0.f;          // reset for the next layer's stats
    g_stats[DH + c] = 0.f;
}

// ---------------- t = sum_n s[n] * relu(bn(g_agg[n,:])) ---------------------
__global__ void treduce_kernel() {
    const int col = threadIdx.x;   // 128 threads
    float sc = g_scale[col], sh = g_shift[col];
    float acc = 0.f;
    for (int r = blockIdx.x; r < NNODES; r += gridDim.x) {
        float v = g_agg[(long)r * DH + col];
        v = fmaxf(0.f, fmaf(v, sc, sh));
        acc = fmaf(g_s[r], v, acc);
    }
    atomicAdd(&g_t[col], acc);
}

// ---------------- out = t @ W2 + N * b2 -------------------------------------
__global__ void final_kernel(const float* __restrict__ W2,
                             const float* __restrict__ b2,
                             float* __restrict__ out) {
    int o = threadIdx.x;   // 64 threads
    float acc = (float)NNODES * b2[o];
#pragma unroll 8
    for (int f = 0; f < DH; f++)
        acc = fmaf(g_t[f], W2[f * DOUT + o], acc);
    out[o] = acc;
}

// ---------------- launch ----------------------------------------------------
extern "C" void kernel_launch(void* const* d_in, const int* in_sizes, int n_in,
                              void* d_out, int out_size) {
    const float* nf     = (const float*)d_in[0];
    const int*   ei     = (const int*)  d_in[1];   // [2][E]
    const float* ew     = (const float*)d_in[2];
    const float* W0     = (const float*)d_in[3];
    const float* W1     = (const float*)d_in[5];
    const float* W2     = (const float*)d_in[7];
    const float* b2     = (const float*)d_in[8];
    const float* gamma0 = (const float*)d_in[9];
    const float* beta0  = (const float*)d_in[10];
    const float* gamma1 = (const float*)d_in[11];
    const float* beta1  = (const float*)d_in[12];
    const int* src = ei;
    const int* dst = ei + NEDGES;
    float* out = (float*)d_out;

    cudaFuncSetAttribute(gemm_kernel,
                         cudaFuncAttributeMaxDynamicSharedMemorySize,
                         (int)GEMM_SMEM);

    // ---- CSR build (reused by both aggregation layers) + src weight sums
    zero_init_kernel<<<(NNODES + 255) / 256, 256>>>();
    hist_kernel<<<(NEDGES + 255) / 256, 256>>>(src, dst, ew);
    scan_kernel<<<1, 1024>>>();
    fill_kernel<<<(NEDGES + 255) / 256, 256>>>(src, dst, ew);

    // ---- layer 0: TF32 GEMM -> CSR gather (stats fused) -> BN params
    gemm_kernel<<<GRID_GEMM, GEMM_THREADS, GEMM_SMEM>>>(nf, W0, 0);
    gather_kernel<<<2048, 256>>>();
    bnparams_kernel<<<1, DH>>>(gamma0, beta0);

    // ---- layer 1: BN+ReLU fused into GEMM tile load
    gemm_kernel<<<GRID_GEMM, GEMM_THREADS, GEMM_SMEM>>>(nullptr, W1, 1);
    gather_kernel<<<2048, 256>>>();
    bnparams_kernel<<<1, DH>>>(gamma1, beta1);

    // ---- layer 2 collapsed: out = (s^T relu(bn(agg1))) @ W2 + N*b2
    treduce_kernel<<<1024, DH>>>();
    final_kernel<<<1, DOUT>>>(W2, b2, out);
}

// round 14
// speedup vs baseline: 1.1436x; 1.1436x over previous
#include <cuda_runtime.h>
#include <cuda_bf16.h>

#define NNODES 100000
#define NEDGES 1600000
#define DH 128
#define DOUT 64
#define BN_EPS 1e-5f

#define TM 64
#define GEMM_THREADS 256
#define XS_STRIDE 132                 // 64 rows  (A tile), bank-spread pad
#define WS_STRIDE 136                 // 128 rows (B tile), bank-spread pad
#define GEMM_SMEM ((DH * WS_STRIDE + TM * XS_STRIDE) * 4)   // ~103.4 KB
#define GRID_GEMM ((NNODES + TM - 1) / TM)

// ---------------- device scratch ----------------
struct alignas(8) Edge { int s; float w; };

__device__ __nv_bfloat16 g_hb[(long)NNODES * DH];    // GEMM output (bf16)
__device__ __nv_bfloat16 g_aggb[(long)NNODES * DH];  // aggregation (bf16)
__device__ float g_s[NNODES];                // per-src edge-weight sums
__device__ float g_stats[2][2 * DH];         // per-layer column sum / sumsq
__device__ float g_t[DH];                    // s^T x1
__device__ int   g_rowptr[NNODES + 1];       // CSR by dst
__device__ int   g_cnt[NNODES];              // histogram / fill cursor
__device__ Edge  g_csr[NEDGES];              // packed (src, weight)

__device__ __forceinline__ unsigned tf32_of(float f) {
    unsigned r;
    asm("cvt.rna.tf32.f32 %0, %1;" : "=r"(r) : "f"(f));
    return r;
}

#define MMA_TF32(d, a, b)                                                    \
    asm volatile(                                                            \
        "mma.sync.aligned.m16n8k8.row.col.f32.tf32.tf32.f32 "                \
        "{%0,%1,%2,%3}, {%4,%5,%6,%7}, {%8,%9}, {%0,%1,%2,%3};"              \
        : "+f"((d)[0]), "+f"((d)[1]), "+f"((d)[2]), "+f"((d)[3])             \
        : "r"((a)[0]), "r"((a)[1]), "r"((a)[2]), "r"((a)[3]),                \
          "r"((b)[0]), "r"((b)[1]))

// ---------------- init: counters, s, stats, t -------------------------------
__global__ void zero_init_kernel() {
    int i = blockIdx.x * blockDim.x + threadIdx.x;
    int stride = gridDim.x * blockDim.x;
    for (int j = i; j < NNODES; j += stride) { g_cnt[j] = 0; g_s[j] = 0.f; }
    if (i < 4 * DH)       ((float*)g_stats)[i] = 0.f;
    else if (i < 5 * DH)  g_t[i - 4 * DH] = 0.f;
}

// ---------------- histogram by dst, fused per-src weight sums ---------------
__global__ void hist_kernel(const int* __restrict__ src,
                            const int* __restrict__ dst,
                            const float* __restrict__ ew) {
    int e = blockIdx.x * blockDim.x + threadIdx.x;
    if (e < NEDGES) {
        atomicAdd(&g_cnt[dst[e]], 1);
        atomicAdd(&g_s[src[e]], ew[e]);
    }
}

// ---------------- exclusive scan of g_cnt -> g_rowptr (single block) --------
__global__ void scan_kernel() {
    __shared__ int ssums[1024];
    const int CH = (NNODES + 1023) / 1024;
    int t = threadIdx.x;
    int base = t * CH;
    int lim = min(base + CH, NNODES);
    int s = 0;
    for (int i = base; i < lim; i++) s += g_cnt[i];
    ssums[t] = s;
    __syncthreads();
    for (int off = 1; off < 1024; off <<= 1) {
        int v = (t >= off) ? ssums[t - off] : 0;
        __syncthreads();
        ssums[t] += v;
        __syncthreads();
    }
    int run = t ? ssums[t - 1] : 0;
    for (int i = base; i < lim; i++) {
        int c = g_cnt[i];
        g_rowptr[i] = run;
        g_cnt[i] = run;          // fill cursor
        run += c;
    }
    if (t == 0) g_rowptr[NNODES] = ssums[1023];
}

// ---------------- fill CSR (single 8B store per edge) ------------------------
__global__ void fill_kernel(const int* __restrict__ src,
                            const int* __restrict__ dst,
                            const float* __restrict__ ew) {
    int e = blockIdx.x * blockDim.x + threadIdx.x;
    if (e < NEDGES) {
        int pos = atomicAdd(&g_cnt[dst[e]], 1);
        Edge ed; ed.s = src[e]; ed.w = ew[e];
        g_csr[pos] = ed;
    }
}

// ---------------- GEMM: g_hb = X @ W via TF32 tensor-core mma ---------------
// mode 0: X = Xext (fp32 raw); mode 1: X = relu(bn(g_aggb)) with inline BN
__global__ void gemm_kernel(const float* __restrict__ Xext,
                            const float* __restrict__ W, int mode,
                            const float* __restrict__ gamma,
                            const float* __restrict__ beta) {
    extern __shared__ unsigned smem_u[];
    unsigned* ws = smem_u;                        // [128][WS_STRIDE] tf32
    unsigned* xs = smem_u + DH * WS_STRIDE;       // [64][XS_STRIDE]  tf32
    __shared__ float ssc[DH], ssh[DH];

    const int tid = threadIdx.x;

    if (mode) {
        if (tid < DH) {
            float mean = g_stats[0][tid] * (1.0f / NNODES);
            float var  = g_stats[0][DH + tid] * (1.0f / NNODES) - mean * mean;
            float sc   = gamma[tid] * rsqrtf(var + BN_EPS);
            ssc[tid] = sc;
            ssh[tid] = beta[tid] - mean * sc;
        }
        __syncthreads();
    }

    // ---- stage W (k-major) as tf32
    for (int i = tid; i < DH * DH / 4; i += GEMM_THREADS) {
        int k  = i >> 5;          // 32 float4 per row
        int c4 = (i & 31) << 2;
        float4 v = ((const float4*)W)[i];
        uint4 o;
        o.x = tf32_of(v.x); o.y = tf32_of(v.y);
        o.z = tf32_of(v.z); o.w = tf32_of(v.w);
        *(uint4*)(ws + k * WS_STRIDE + c4) = o;
    }

    // ---- stage X tile (fused BN+ReLU for mode 1) as tf32
    const int row0 = blockIdx.x * TM;
    for (int i = tid; i < TM * DH / 4; i += GEMM_THREADS) {
        int r  = i >> 5;
        int c4 = (i & 31) << 2;
        float4 v = make_float4(0.f, 0.f, 0.f, 0.f);
        if (row0 + r < NNODES) {
            if (mode) {
                uint2 u = *(const uint2*)(g_aggb + (long)(row0 + r) * DH + c4);
                float2 f01 = __bfloat1622float2(*(__nv_bfloat162*)&u.x);
                float2 f23 = __bfloat1622float2(*(__nv_bfloat162*)&u.y);
                v.x = fmaxf(0.f, fmaf(f01.x, ssc[c4 + 0], ssh[c4 + 0]));
                v.y = fmaxf(0.f, fmaf(f01.y, ssc[c4 + 1], ssh[c4 + 1]));
                v.z = fmaxf(0.f, fmaf(f23.x, ssc[c4 + 2], ssh[c4 + 2]));
                v.w = fmaxf(0.f, fmaf(f23.y, ssc[c4 + 3], ssh[c4 + 3]));
            } else {
                v = *(const float4*)(Xext + (long)(row0 + r) * DH + c4);
            }
        }
        uint4 o;
        o.x = tf32_of(v.x); o.y = tf32_of(v.y);
        o.z = tf32_of(v.z); o.w = tf32_of(v.w);
        *(uint4*)(xs + r * XS_STRIDE + c4) = o;
    }
    __syncthreads();

    const int lane = tid & 31;
    const int warp = tid >> 5;
    const int mrow = (warp & 1) * 32;
    const int ncol = (warp >> 1) * 32;

    float acc[2][4][4];
#pragma unroll
    for (int mi = 0; mi < 2; mi++)
#pragma unroll
        for (int ni = 0; ni < 4; ni++)
#pragma unroll
            for (int j = 0; j < 4; j++) acc[mi][ni][j] = 0.f;

    const int ar = mrow + (lane >> 2);
    const int ak = lane & 3;
    const int bn = ncol + (lane >> 2);
    const int bk = lane & 3;

#pragma unroll 4
    for (int k0 = 0; k0 < DH; k0 += 8) {
        unsigned a[2][4], b[4][2];
#pragma unroll
        for (int mi = 0; mi < 2; mi++) {
            const unsigned* ab = xs + (ar + 16 * mi) * XS_STRIDE + k0 + ak;
            a[mi][0] = ab[0];
            a[mi][1] = ab[8 * XS_STRIDE];
            a[mi][2] = ab[4];
            a[mi][3] = ab[8 * XS_STRIDE + 4];
        }
#pragma unroll
        for (int ni = 0; ni < 4; ni++) {
            const unsigned* bb = ws + (k0 + bk) * WS_STRIDE + bn + 8 * ni;
            b[ni][0] = bb[0];
            b[ni][1] = bb[4 * WS_STRIDE];
        }
#pragma unroll
        for (int mi = 0; mi < 2; mi++)
#pragma unroll
            for (int ni = 0; ni < 4; ni++)
                MMA_TF32(acc[mi][ni], a[mi], b[ni]);
    }

    // ---- epilogue: bf16 pairs
#pragma unroll
    for (int mi = 0; mi < 2; mi++) {
        int r0 = row0 + mrow + 16 * mi + (lane >> 2);
        int r1 = r0 + 8;
#pragma unroll
        for (int ni = 0; ni < 4; ni++) {
            int cc = ncol + 8 * ni + 2 * (lane & 3);
            if (r0 < NNODES)
                *(__nv_bfloat162*)(g_hb + (long)r0 * DH + cc) =
                    __floats2bfloat162_rn(acc[mi][ni][0], acc[mi][ni][1]);
            if (r1 < NNODES)
                *(__nv_bfloat162*)(g_hb + (long)r1 * DH + cc) =
                    __floats2bfloat162_rn(acc[mi][ni][2], acc[mi][ni][3]);
        }
    }
}

// ---------------- CSR gather-aggregate (bf16 in/out) with fused stats -------
// one warp per node; lane owns 4 columns; 8 edges in flight
__device__ __forceinline__ void acc_edge(float4& acc, uint2 u, float w) {
    float2 f01 = __bfloat1622float2(*(__nv_bfloat162*)&u.x);
    float2 f23 = __bfloat1622float2(*(__nv_bfloat162*)&u.y);
    acc.x = fmaf(w, f01.x, acc.x); acc.y = fmaf(w, f01.y, acc.y);
    acc.z = fmaf(w, f23.x, acc.z); acc.w = fmaf(w, f23.y, acc.w);
}

__global__ void gather_kernel(int layer) {
    __shared__ float sred[8][DH];
    __shared__ float sred2[8][DH];
    const int tid = threadIdx.x;
    const int lane = tid & 31;
    const int warp = tid >> 5;

    float4 lsum = make_float4(0.f, 0.f, 0.f, 0.f);
    float4 lsq  = make_float4(0.f, 0.f, 0.f, 0.f);

    for (int n = blockIdx.x * 8 + warp; n < NNODES; n += gridDim.x * 8) {
        int beg = g_rowptr[n], end = g_rowptr[n + 1];
        float4 acc = make_float4(0.f, 0.f, 0.f, 0.f);
        int j = beg;
        for (; j + 8 <= end; j += 8) {
            Edge  e[8];
            uint2 u[8];
#pragma unroll
            for (int q = 0; q < 8; q++) e[q] = g_csr[j + q];
#pragma unroll
            for (int q = 0; q < 8; q++)
                u[q] = ((const uint2*)(g_hb + (long)e[q].s * DH))[lane];
#pragma unroll
            for (int q = 0; q < 8; q++) acc_edge(acc, u[q], e[q].w);
        }
        for (; j < end; j++) {
            Edge e0 = g_csr[j];
            uint2 u0 = ((const uint2*)(g_hb + (long)e0.s * DH))[lane];
            acc_edge(acc, u0, e0.w);
        }
        *(uint2*)(g_aggb + (long)n * DH + lane * 4) =
            *(uint2*)&(__nv_bfloat162[2]){
                __floats2bfloat162_rn(acc.x, acc.y),
                __floats2bfloat162_rn(acc.z, acc.w)};

        lsum.x += acc.x; lsum.y += acc.y; lsum.z += acc.z; lsum.w += acc.w;
        lsq.x = fmaf(acc.x, acc.x, lsq.x); lsq.y = fmaf(acc.y, acc.y, lsq.y);
        lsq.z = fmaf(acc.z, acc.z, lsq.z); lsq.w = fmaf(acc.w, acc.w, lsq.w);
    }

    sred[warp][lane * 4 + 0] = lsum.x;  sred2[warp][lane * 4 + 0] = lsq.x;
    sred[warp][lane * 4 + 1] = lsum.y;  sred2[warp][lane * 4 + 1] = lsq.y;
    sred[warp][lane * 4 + 2] = lsum.z;  sred2[warp][lane * 4 + 2] = lsq.z;
    sred[warp][lane * 4 + 3] = lsum.w;  sred2[warp][lane * 4 + 3] = lsq.w;
    __syncthreads();
    if (tid < DH) {
        float a = 0.f, b = 0.f;
#pragma unroll
        for (int w = 0; w < 8; w++) { a += sred[w][tid]; b += sred2[w][tid]; }
        atomicAdd(&g_stats[layer][tid], a);
        atomicAdd(&g_stats[layer][DH + tid], b);
    }
}

// ---------------- t = sum_n s[n] * relu(bn1(g_aggb[n,:])) -------------------
// warp per row, 8 rows in flight per block; inline BN params from stats[1]
__global__ void treduce_kernel(const float* __restrict__ gamma,
                               const float* __restrict__ beta) {
    __shared__ float sred[8][DH];
    __shared__ float ssc[DH], ssh[DH];
    const int tid = threadIdx.x;
    const int lane = tid & 31;
    const int warp = tid >> 5;

    if (tid < DH) {
        float mean = g_stats[1][tid] * (1.0f / NNODES);
        float var  = g_stats[1][DH + tid] * (1.0f / NNODES) - mean * mean;
        float sc   = gamma[tid] * rsqrtf(var + BN_EPS);
        ssc[tid] = sc;
        ssh[tid] = beta[tid] - mean * sc;
    }
    __syncthreads();

    float4 sc4 = *(float4*)(ssc + lane * 4);
    float4 sh4 = *(float4*)(ssh + lane * 4);

    float4 lsum = make_float4(0.f, 0.f, 0.f, 0.f);
    for (int n = blockIdx.x * 8 + warp; n < NNODES; n += gridDim.x * 8) {
        float sn = g_s[n];
        uint2 u = *(const uint2*)(g_aggb + (long)n * DH + lane * 4);
        float2 f01 = __bfloat1622float2(*(__nv_bfloat162*)&u.x);
        float2 f23 = __bfloat1622float2(*(__nv_bfloat162*)&u.y);
        float v0 = fmaxf(0.f, fmaf(f01.x, sc4.x, sh4.x));
        float v1 = fmaxf(0.f, fmaf(f01.y, sc4.y, sh4.y));
        float v2 = fmaxf(0.f, fmaf(f23.x, sc4.z, sh4.z));
        float v3 = fmaxf(0.f, fmaf(f23.y, sc4.w, sh4.w));
        lsum.x = fmaf(sn, v0, lsum.x);
        lsum.y = fmaf(sn, v1, lsum.y);
        lsum.z = fmaf(sn, v2, lsum.z);
        lsum.w = fmaf(sn, v3, lsum.w);
    }

    sred[warp][lane * 4 + 0] = lsum.x;
    sred[warp][lane * 4 + 1] = lsum.y;
    sred[warp][lane * 4 + 2] = lsum.z;
    sred[warp][lane * 4 + 3] = lsum.w;
    __syncthreads();
    if (tid < DH) {
        float a = 0.f;
#pragma unroll
        for (int w = 0; w < 8; w++) a += sred[w][tid];
        atomicAdd(&g_t[tid], a);
    }
}

// ---------------- out = t @ W2 + N * b2 -------------------------------------
__global__ void final_kernel(const float* __restrict__ W2,
                             const float* __restrict__ b2,
                             float* __restrict__ out) {
    int o = threadIdx.x;   // 64 threads
    float acc = (float)NNODES * b2[o];
#pragma unroll 8
    for (int f = 0; f < DH; f++)
        acc = fmaf(g_t[f], W2[f * DOUT + o], acc);
    out[o] = acc;
}

// ---------------- launch ----------------------------------------------------
extern "C" void kernel_launch(void* const* d_in, const int* in_sizes, int n_in,
                              void* d_out, int out_size) {
    const float* nf     = (const float*)d_in[0];
    const int*   ei     = (const int*)  d_in[1];   // [2][E]
    const float* ew     = (const float*)d_in[2];
    const float* W0     = (const float*)d_in[3];
    const float* W1     = (const float*)d_in[5];
    const float* W2     = (const float*)d_in[7];
    const float* b2     = (const float*)d_in[8];
    const float* gamma0 = (const float*)d_in[9];
    const float* beta0  = (const float*)d_in[10];
    const float* gamma1 = (const float*)d_in[11];
    const float* beta1  = (const float*)d_in[12];
    const int* src = ei;
    const int* dst = ei + NEDGES;
    float* out = (float*)d_out;

    cudaFuncSetAttribute(gemm_kernel,
                         cudaFuncAttributeMaxDynamicSharedMemorySize,
                         (int)GEMM_SMEM);

    // ---- CSR build (reused by both aggregation layers) + src weight sums
    zero_init_kernel<<<(NNODES + 255) / 256, 256>>>();
    hist_kernel<<<(NEDGES + 255) / 256, 256>>>(src, dst, ew);
    scan_kernel<<<1, 1024>>>();
    fill_kernel<<<(NEDGES + 255) / 256, 256>>>(src, dst, ew);

    // ---- layer 0: TF32 GEMM -> CSR gather (stats fused)
    gemm_kernel<<<GRID_GEMM, GEMM_THREADS, GEMM_SMEM>>>(nf, W0, 0, nullptr, nullptr);
    gather_kernel<<<2048, 256>>>(0);

    // ---- layer 1: BN0+ReLU fused into GEMM tile load (inline BN params)
    gemm_kernel<<<GRID_GEMM, GEMM_THREADS, GEMM_SMEM>>>(nullptr, W1, 1, gamma0, beta0);
    gather_kernel<<<2048, 256>>>(1);

    // ---- layer 2 collapsed: out = (s^T relu(bn1(agg1))) @ W2 + N*b2
    treduce_kernel<<<2048, 256>>>(gamma1, beta1);
    final_kernel<<<1, DOUT>>>(W2, b2, out);
}

// round 16
// speedup vs baseline: 1.6566x; 1.4485x over previous
#include <cuda_runtime.h>
#include <cuda_bf16.h>

#define NNODES 100000
#define NEDGES 1600000
#define DH 128
#define DOUT 64
#define BN_EPS 1e-5f

#define TM 64
#define GEMM_THREADS 256
#define XS_STRIDE 132                 // 64 rows  (A tile), bank-spread pad
#define WS_STRIDE 136                 // 128 rows (B tile), bank-spread pad
#define GEMM_SMEM ((DH * WS_STRIDE + TM * XS_STRIDE) * 4)   // ~103.4 KB
#define GRID_GEMM ((NNODES + TM - 1) / TM)
#define HIST_BLOCKS ((NEDGES + 255) / 256)

// ---------------- device scratch ----------------
struct alignas(8) Edge { int s; float w; };

__device__ __nv_bfloat16 g_hb[(long)NNODES * DH];    // GEMM output (bf16)
__device__ __nv_bfloat16 g_aggb[(long)NNODES * DH];  // aggregation (bf16)
__device__ float g_s[NNODES];                // per-src edge-weight sums
__device__ float g_stats[2][2 * DH];         // per-layer column sum / sumsq
__device__ float g_t[DH];                    // s^T x1
__device__ int   g_rowptr[NNODES];           // CSR segment begin (by dst)
__device__ int   g_cnt[NNODES];              // histogram / cursor / seg end
__device__ int   g_total;                    // segment allocator
__device__ Edge  g_csr[NEDGES];              // packed (src, weight)

__device__ __forceinline__ unsigned tf32_of(float f) {
    unsigned r;
    asm("cvt.rna.tf32.f32 %0, %1;" : "=r"(r) : "f"(f));
    return r;
}

#define MMA_TF32(d, a, b)                                                    \
    asm volatile(                                                            \
        "mma.sync.aligned.m16n8k8.row.col.f32.tf32.tf32.f32 "                \
        "{%0,%1,%2,%3}, {%4,%5,%6,%7}, {%8,%9}, {%0,%1,%2,%3};"              \
        : "+f"((d)[0]), "+f"((d)[1]), "+f"((d)[2]), "+f"((d)[3])             \
        : "r"((a)[0]), "r"((a)[1]), "r"((a)[2]), "r"((a)[3]),                \
          "r"((b)[0]), "r"((b)[1]))

// ---------------- init: counters, s, stats, t, allocator --------------------
__global__ void zero_init_kernel() {
    int i = blockIdx.x * blockDim.x + threadIdx.x;
    int stride = gridDim.x * blockDim.x;
    for (int j = i; j < NNODES; j += stride) { g_cnt[j] = 0; g_s[j] = 0.f; }
    if (i < 4 * DH)       ((float*)g_stats)[i] = 0.f;
    else if (i < 5 * DH)  g_t[i - 4 * DH] = 0.f;
    if (i == 5 * DH)      g_total = 0;
}

// ---------------- GEMM body: g_hb = X @ W via TF32 tensor-core mma ----------
// mode 0: X = Xext (fp32 raw); mode 1: X = relu(bn0(g_aggb)) with inline BN
__device__ __forceinline__ void gemm_body(const float* __restrict__ Xext,
                                          const float* __restrict__ W,
                                          int mode, int blk,
                                          const float* __restrict__ gamma,
                                          const float* __restrict__ beta) {
    extern __shared__ unsigned smem_u[];
    unsigned* ws = smem_u;                        // [128][WS_STRIDE] tf32
    unsigned* xs = smem_u + DH * WS_STRIDE;       // [64][XS_STRIDE]  tf32
    __shared__ float ssc[DH], ssh[DH];

    const int tid = threadIdx.x;

    if (mode) {
        if (tid < DH) {
            float mean = g_stats[0][tid] * (1.0f / NNODES);
            float var  = g_stats[0][DH + tid] * (1.0f / NNODES) - mean * mean;
            float sc   = gamma[tid] * rsqrtf(var + BN_EPS);
            ssc[tid] = sc;
            ssh[tid] = beta[tid] - mean * sc;
        }
        __syncthreads();
    }

    // ---- stage W (k-major) as tf32
    for (int i = tid; i < DH * DH / 4; i += GEMM_THREADS) {
        int k  = i >> 5;          // 32 float4 per row
        int c4 = (i & 31) << 2;
        float4 v = ((const float4*)W)[i];
        uint4 o;
        o.x = tf32_of(v.x); o.y = tf32_of(v.y);
        o.z = tf32_of(v.z); o.w = tf32_of(v.w);
        *(uint4*)(ws + k * WS_STRIDE + c4) = o;
    }

    // ---- stage X tile (fused BN+ReLU for mode 1) as tf32
    const int row0 = blk * TM;
    for (int i = tid; i < TM * DH / 4; i += GEMM_THREADS) {
        int r  = i >> 5;
        int c4 = (i & 31) << 2;
        float4 v = make_float4(0.f, 0.f, 0.f, 0.f);
        if (row0 + r < NNODES) {
            if (mode) {
                uint2 u = *(const uint2*)(g_aggb + (long)(row0 + r) * DH + c4);
                float2 f01 = __bfloat1622float2(*(__nv_bfloat162*)&u.x);
                float2 f23 = __bfloat1622float2(*(__nv_bfloat162*)&u.y);
                v.x = fmaxf(0.f, fmaf(f01.x, ssc[c4 + 0], ssh[c4 + 0]));
                v.y = fmaxf(0.f, fmaf(f01.y, ssc[c4 + 1], ssh[c4 + 1]));
                v.z = fmaxf(0.f, fmaf(f23.x, ssc[c4 + 2], ssh[c4 + 2]));
                v.w = fmaxf(0.f, fmaf(f23.y, ssc[c4 + 3], ssh[c4 + 3]));
            } else {
                v = *(const float4*)(Xext + (long)(row0 + r) * DH + c4);
            }
        }
        uint4 o;
        o.x = tf32_of(v.x); o.y = tf32_of(v.y);
        o.z = tf32_of(v.z); o.w = tf32_of(v.w);
        *(uint4*)(xs + r * XS_STRIDE + c4) = o;
    }
    __syncthreads();

    const int lane = tid & 31;
    const int warp = tid >> 5;
    const int mrow = (warp & 1) * 32;
    const int ncol = (warp >> 1) * 32;

    float acc[2][4][4];
#pragma unroll
    for (int mi = 0; mi < 2; mi++)
#pragma unroll
        for (int ni = 0; ni < 4; ni++)
#pragma unroll
            for (int j = 0; j < 4; j++) acc[mi][ni][j] = 0.f;

    const int ar = mrow + (lane >> 2);
    const int ak = lane & 3;
    const int bn = ncol + (lane >> 2);
    const int bk = lane & 3;

#pragma unroll 4
    for (int k0 = 0; k0 < DH; k0 += 8) {
        unsigned a[2][4], b[4][2];
#pragma unroll
        for (int mi = 0; mi < 2; mi++) {
            const unsigned* ab = xs + (ar + 16 * mi) * XS_STRIDE + k0 + ak;
            a[mi][0] = ab[0];
            a[mi][1] = ab[8 * XS_STRIDE];
            a[mi][2] = ab[4];
            a[mi][3] = ab[8 * XS_STRIDE + 4];
        }
#pragma unroll
        for (int ni = 0; ni < 4; ni++) {
            const unsigned* bb = ws + (k0 + bk) * WS_STRIDE + bn + 8 * ni;
            b[ni][0] = bb[0];
            b[ni][1] = bb[4 * WS_STRIDE];
        }
#pragma unroll
        for (int mi = 0; mi < 2; mi++)
#pragma unroll
            for (int ni = 0; ni < 4; ni++)
                MMA_TF32(acc[mi][ni], a[mi], b[ni]);
    }

    // ---- epilogue: bf16 pairs
#pragma unroll
    for (int mi = 0; mi < 2; mi++) {
        int r0 = row0 + mrow + 16 * mi + (lane >> 2);
        int r1 = r0 + 8;
#pragma unroll
        for (int ni = 0; ni < 4; ni++) {
            int cc = ncol + 8 * ni + 2 * (lane & 3);
            if (r0 < NNODES)
                *(__nv_bfloat162*)(g_hb + (long)r0 * DH + cc) =
                    __floats2bfloat162_rn(acc[mi][ni][0], acc[mi][ni][1]);
            if (r1 < NNODES)
                *(__nv_bfloat162*)(g_hb + (long)r1 * DH + cc) =
                    __floats2bfloat162_rn(acc[mi][ni][2], acc[mi][ni][3]);
        }
    }
}

// ---------------- fat kernel: gemm0 blocks + hist blocks (independent) ------
__global__ void gemm0_hist_kernel(const float* __restrict__ Xext,
                                  const float* __restrict__ W,
                                  const int* __restrict__ src,
                                  const int* __restrict__ dst,
                                  const float* __restrict__ ew) {
    if (blockIdx.x >= GRID_GEMM) {
        // histogram by dst + fused per-src weight sums
        int e = (blockIdx.x - GRID_GEMM) * blockDim.x + threadIdx.x;
        if (e < NEDGES) {
            atomicAdd(&g_cnt[dst[e]], 1);
            atomicAdd(&g_s[src[e]], ew[e]);
        }
        return;
    }
    gemm_body(Xext, W, 0, blockIdx.x, nullptr, nullptr);
}

__global__ void gemm1_kernel(const float* __restrict__ W,
                             const float* __restrict__ gamma,
                             const float* __restrict__ beta) {
    gemm_body(nullptr, W, 1, blockIdx.x, gamma, beta);
}

// ---------------- parallel segment allocation (order-free CSR) --------------
__global__ void alloc_kernel() {
    int n = blockIdx.x * blockDim.x + threadIdx.x;
    if (n < NNODES) {
        int c = g_cnt[n];
        int pos = atomicAdd(&g_total, c);
        g_rowptr[n] = pos;
        g_cnt[n] = pos;           // fill cursor; after fill == segment end
    }
}

// ---------------- fill CSR (single 8B store per edge) ------------------------
__global__ void fill_kernel(const int* __restrict__ src,
                            const int* __restrict__ dst,
                            const float* __restrict__ ew) {
    int e = blockIdx.x * blockDim.x + threadIdx.x;
    if (e < NEDGES) {
        int pos = atomicAdd(&g_cnt[dst[e]], 1);
        Edge ed; ed.s = src[e]; ed.w = ew[e];
        g_csr[pos] = ed;
    }
}

// ---------------- CSR gather-aggregate (bf16 in/out) with fused stats -------
// one warp per node; lane owns 4 columns; 8 edges in flight
__device__ __forceinline__ void acc_edge(float4& acc, uint2 u, float w) {
    float2 f01 = __bfloat1622float2(*(__nv_bfloat162*)&u.x);
    float2 f23 = __bfloat1622float2(*(__nv_bfloat162*)&u.y);
    acc.x = fmaf(w, f01.x, acc.x); acc.y = fmaf(w, f01.y, acc.y);
    acc.z = fmaf(w, f23.x, acc.z); acc.w = fmaf(w, f23.y, acc.w);
}

__global__ void gather_kernel(int layer) {
    __shared__ float sred[8][DH];
    __shared__ float sred2[8][DH];
    const int tid = threadIdx.x;
    const int lane = tid & 31;
    const int warp = tid >> 5;

    float4 lsum = make_float4(0.f, 0.f, 0.f, 0.f);
    float4 lsq  = make_float4(0.f, 0.f, 0.f, 0.f);

    for (int n = blockIdx.x * 8 + warp; n < NNODES; n += gridDim.x * 8) {
        int beg = g_rowptr[n], end = g_cnt[n];   // cursor == segment end
        float4 acc = make_float4(0.f, 0.f, 0.f, 0.f);
        int j = beg;
        for (; j + 8 <= end; j += 8) {
            Edge  e[8];
            uint2 u[8];
#pragma unroll
            for (int q = 0; q < 8; q++) e[q] = g_csr[j + q];
#pragma unroll
            for (int q = 0; q < 8; q++)
                u[q] = ((const uint2*)(g_hb + (long)e[q].s * DH))[lane];
#pragma unroll
            for (int q = 0; q < 8; q++) acc_edge(acc, u[q], e[q].w);
        }
        for (; j < end; j++) {
            Edge e0 = g_csr[j];
            uint2 u0 = ((const uint2*)(g_hb + (long)e0.s * DH))[lane];
            acc_edge(acc, u0, e0.w);
        }
        *(uint2*)(g_aggb + (long)n * DH + lane * 4) =
            *(uint2*)&(__nv_bfloat162[2]){
                __floats2bfloat162_rn(acc.x, acc.y),
                __floats2bfloat162_rn(acc.z, acc.w)};

        lsum.x += acc.x; lsum.y += acc.y; lsum.z += acc.z; lsum.w += acc.w;
        lsq.x = fmaf(acc.x, acc.x, lsq.x); lsq.y = fmaf(acc.y, acc.y, lsq.y);
        lsq.z = fmaf(acc.z, acc.z, lsq.z); lsq.w = fmaf(acc.w, acc.w, lsq.w);
    }

    sred[warp][lane * 4 + 0] = lsum.x;  sred2[warp][lane * 4 + 0] = lsq.x;
    sred[warp][lane * 4 + 1] = lsum.y;  sred2[warp][lane * 4 + 1] = lsq.y;
    sred[warp][lane * 4 + 2] = lsum.z;  sred2[warp][lane * 4 + 2] = lsq.z;
    sred[warp][lane * 4 + 3] = lsum.w;  sred2[warp][lane * 4 + 3] = lsq.w;
    __syncthreads();
    if (tid < DH) {
        float a = 0.f, b = 0.f;
#pragma unroll
        for (int w = 0; w < 8; w++) { a += sred[w][tid]; b += sred2[w][tid]; }
        atomicAdd(&g_stats[layer][tid], a);
        atomicAdd(&g_stats[layer][DH + tid], b);
    }
}

// ---------------- t = sum_n s[n] * relu(bn1(g_aggb[n,:])) -------------------
__global__ void treduce_kernel(const float* __restrict__ gamma,
                               const float* __restrict__ beta) {
    __shared__ float sred[8][DH];
    __shared__ float ssc[DH], ssh[DH];
    const int tid = threadIdx.x;
    const int lane = tid & 31;
    const int warp = tid >> 5;

    if (tid < DH) {
        float mean = g_stats[1][tid] * (1.0f / NNODES);
        float var  = g_stats[1][DH + tid] * (1.0f / NNODES) - mean * mean;
        float sc   = gamma[tid] * rsqrtf(var + BN_EPS);
        ssc[tid] = sc;
        ssh[tid] = beta[tid] - mean * sc;
    }
    __syncthreads();

    float4 sc4 = *(float4*)(ssc + lane * 4);
    float4 sh4 = *(float4*)(ssh + lane * 4);

    float4 lsum = make_float4(0.f, 0.f, 0.f, 0.f);
    for (int n = blockIdx.x * 8 + warp; n < NNODES; n += gridDim.x * 8) {
        float sn = g_s[n];
        uint2 u = *(const uint2*)(g_aggb + (long)n * DH + lane * 4);
        float2 f01 = __bfloat1622float2(*(__nv_bfloat162*)&u.x);
        float2 f23 = __bfloat1622float2(*(__nv_bfloat162*)&u.y);
        float v0 = fmaxf(0.f, fmaf(f01.x, sc4.x, sh4.x));
        float v1 = fmaxf(0.f, fmaf(f01.y, sc4.y, sh4.y));
        float v2 = fmaxf(0.f, fmaf(f23.x, sc4.z, sh4.z));
        float v3 = fmaxf(0.f, fmaf(f23.y, sc4.w, sh4.w));
        lsum.x = fmaf(sn, v0, lsum.x);
        lsum.y = fmaf(sn, v1, lsum.y);
        lsum.z = fmaf(sn, v2, lsum.z);
        lsum.w = fmaf(sn, v3, lsum.w);
    }

    sred[warp][lane * 4 + 0] = lsum.x;
    sred[warp][lane * 4 + 1] = lsum.y;
    sred[warp][lane * 4 + 2] = lsum.z;
    sred[warp][lane * 4 + 3] = lsum.w;
    __syncthreads();
    if (tid < DH) {
        float a = 0.f;
#pragma unroll
        for (int w = 0; w < 8; w++) a += sred[w][tid];
        atomicAdd(&g_t[tid], a);
    }
}

// ---------------- out = t @ W2 + N * b2 -------------------------------------
__global__ void final_kernel(const float* __restrict__ W2,
                             const float* __restrict__ b2,
                             float* __restrict__ out) {
    int o = threadIdx.x;   // 64 threads
    float acc = (float)NNODES * b2[o];
#pragma unroll 8
    for (int f = 0; f < DH; f++)
        acc = fmaf(g_t[f], W2[f * DOUT + o], acc);
    out[o] = acc;
}

// ---------------- launch ----------------------------------------------------
extern "C" void kernel_launch(void* const* d_in, const int* in_sizes, int n_in,
                              void* d_out, int out_size) {
    const float* nf     = (const float*)d_in[0];
    const int*   ei     = (const int*)  d_in[1];   // [2][E]
    const float* ew     = (const float*)d_in[2];
    const float* W0     = (const float*)d_in[3];
    const float* W1     = (const float*)d_in[5];
    const float* W2     = (const float*)d_in[7];
    const float* b2     = (const float*)d_in[8];
    const float* gamma0 = (const float*)d_in[9];
    const float* beta0  = (const float*)d_in[10];
    const float* gamma1 = (const float*)d_in[11];
    const float* beta1  = (const float*)d_in[12];
    const int* src = ei;
    const int* dst = ei + NEDGES;
    float* out = (float*)d_out;

    cudaFuncSetAttribute(gemm0_hist_kernel,
                         cudaFuncAttributeMaxDynamicSharedMemorySize,
                         (int)GEMM_SMEM);
    cudaFuncSetAttribute(gemm1_kernel,
                         cudaFuncAttributeMaxDynamicSharedMemorySize,
                         (int)GEMM_SMEM);

    // ---- init, then overlap gemm0 with dst-histogram (independent work)
    zero_init_kernel<<<(NNODES + 255) / 256, 256>>>();
    gemm0_hist_kernel<<<GRID_GEMM + HIST_BLOCKS, GEMM_THREADS, GEMM_SMEM>>>(
        nf, W0, src, dst, ew);

    // ---- order-free CSR segment allocation + fill
    alloc_kernel<<<(NNODES + 255) / 256, 256>>>();
    fill_kernel<<<HIST_BLOCKS, 256>>>(src, dst, ew);

    // ---- layer 0 aggregation (stats fused)
    gather_kernel<<<2048, 256>>>(0);

    // ---- layer 1: BN0+ReLU fused into GEMM tile load (inline BN params)
    gemm1_kernel<<<GRID_GEMM, GEMM_THREADS, GEMM_SMEM>>>(W1, gamma0, beta0);
    gather_kernel<<<2048, 256>>>(1);

    // ---- layer 2 collapsed: out = (s^T relu(bn1(agg1))) @ W2 + N*b2
    treduce_kernel<<<2048, 256>>>(gamma1, beta1);
    final_kernel<<<1, DOUT>>>(W2, b2, out);
}